// round 11
// baseline (speedup 1.0000x reference)
#include <cuda_runtime.h>
#include <cuda_bf16.h>

// VolumeSDF renderer: one warp per ray, two-phase march (64+64 samples),
// 2 samples per lane per phase.
//
//   density = ALPHA * LaplaceCDF(-sdf; BETA)
//   tau_s   = density_s * delta_s,  delta = diff(depth), last = 1e10
//   T_s     = exp(-inclusive_cumsum(tau)_s);  w_s = T_s*(1-exp(-tau_s+eps))
//   out[n]  = sum_s w_s * color[n,s,:]
//
// All exponentials in base 2 (single EX2 each); the cumsum is carried in
// log2-units with constants pre-folded.
//
// Byte savings:
//  - phase 2 (samples 64-127) is skipped ENTIRELY (incl. sdf/depth loads)
//    when cum64 >= 9.5 nats: tail weight telescopes to <= exp(-9.5).
//    Warp-uniform branch -> no divergence.
//  - within phase 2, each lane's color load is gated on its own prefix.

#define FAR_DELTA 1e10f
#define AEXP   28.853900817779268f   // (1/BETA)*log2(e) = 20*1.442695
#define DENS2  14.426950408889634f   // ALPHA*log2(e)
#define EPS2   1.442695041e-10f      // EPS*log2(e)
#define SKIP2  13.705602888444545f   // 9.5*log2(e) (nats->bits)

__device__ __forceinline__ float ex2(float x) {
    float y;
    asm("ex2.approx.ftz.f32 %0, %1;" : "=f"(y) : "f"(x));
    return y;
}

// tau per unit delta, in base-2 units: DENS2 * LaplaceCDF(-x, BETA)
__device__ __forceinline__ float dens2(float x) {
    const float e = 0.5f * ex2(-fabsf(x) * AEXP);
    const float cdf = (x > 0.0f) ? e : (1.0f - e);
    return DENS2 * cdf;
}

__global__ __launch_bounds__(256)
void volume_sdf_render_kernel(const float* __restrict__ sdf,
                              const float* __restrict__ color,
                              const float* __restrict__ depth,
                              float* __restrict__ out,
                              int N)
{
    const int gtid = blockIdx.x * blockDim.x + threadIdx.x;
    const int ray  = gtid >> 5;          // one warp per ray
    const int lane = threadIdx.x & 31;
    if (ray >= N) return;

    const int S = 128;
    const long long rbase = (long long)ray * S;
    const long long base1 = rbase + lane * 2;        // samples 2l, 2l+1

    // ---- Phase 1 loads (front-batched: 5 vector loads + 1 broadcast) ----
    const float2 s1 = *reinterpret_cast<const float2*>(sdf   + base1);
    const float2 d1 = *reinterpret_cast<const float2*>(depth + base1);
    const float  d64 = depth[rbase + 64];            // uniform-address broadcast
    const long long cb1 = base1 * 3;                 // 6 floats per lane, 8B-aligned
    const float2 ca = *reinterpret_cast<const float2*>(color + cb1);
    const float2 cm = *reinterpret_cast<const float2*>(color + cb1 + 2);
    const float2 cz = *reinterpret_cast<const float2*>(color + cb1 + 4);

    // Deltas. depth[2l+2] is next lane's d1.x; lane 31 uses depth[64].
    const float dn1 = __shfl_down_sync(0xffffffffu, d1.x, 1);
    const float del0 = d1.y - d1.x;
    const float del1 = ((lane == 31) ? d64 : dn1) - d1.y;

    // tau (base-2), transmittance terms. u = exp2(-tau2+eps2) = 1-trans.
    const float t0 = dens2(s1.x) * del0;
    const float t1 = dens2(s1.y) * del1;
    const float u0 = ex2(-t0 + EPS2);
    const float u1 = ex2(-t1 + EPS2);

    // Lane-local inclusive sums, then warp scan of lane totals.
    const float c0 = t0;
    const float c1 = t0 + t1;
    float incl = c1;
#pragma unroll
    for (int off = 1; off < 32; off <<= 1) {
        const float v = __shfl_up_sync(0xffffffffu, incl, off);
        if (lane >= off) incl += v;
    }
    // Exclusive prefix from the PREVIOUS lane's inclusive value (never by
    // subtraction: the far-delta tau cancels catastrophically — R1/R2 bug).
    float pre = __shfl_up_sync(0xffffffffu, incl, 1);
    if (lane == 0) pre = 0.0f;
    const float cum64 = __shfl_sync(0xffffffffu, incl, 31);

    // Weights: T0 = 2^-(pre+c0); T1 = T0 * 2^-t1 = T0*u1 (eps factor ~1).
    const float T0 = ex2(-(pre + c0));
    const float w0 = T0 * (1.0f - u0);
    const float w1 = (T0 * u1) * (1.0f - u1);

    // sample0 rgb = (ca.x, ca.y, cm.x); sample1 rgb = (cm.y, cz.x, cz.y)
    float r = w0 * ca.x + w1 * cm.y;
    float g = w0 * ca.y + w1 * cz.x;
    float b = w0 * cm.x + w1 * cz.y;

    // ---- Phase 2 (samples 64-127), warp-uniform skip ----
    if (cum64 < SKIP2) {
        const long long base2 = base1 + 64;
        const float2 s2 = *reinterpret_cast<const float2*>(sdf   + base2);
        const float2 d2 = *reinterpret_cast<const float2*>(depth + base2);

        const float dn2 = __shfl_down_sync(0xffffffffu, d2.x, 1);
        const float del0B = d2.y - d2.x;
        const float del1B = (lane == 31) ? FAR_DELTA : (dn2 - d2.y);

        const float t0B = dens2(s2.x) * del0B;
        const float t1B = dens2(s2.y) * del1B;
        const float u0B = ex2(-t0B + EPS2);
        const float u1B = ex2(-t1B + EPS2);

        const float c0B = t0B;
        const float c1B = t0B + t1B;
        float inclB = c1B;
#pragma unroll
        for (int off = 1; off < 32; off <<= 1) {
            const float v = __shfl_up_sync(0xffffffffu, inclB, off);
            if (lane >= off) inclB += v;
        }
        float preB = __shfl_up_sync(0xffffffffu, inclB, 1);
        if (lane == 0) preB = 0.0f;
        preB += cum64;

        // Per-lane gate: tail past this lane is <= 2^-preB.
        if (preB < SKIP2) {
            const long long cb2 = base2 * 3;
            const float2 da = *reinterpret_cast<const float2*>(color + cb2);
            const float2 dm = *reinterpret_cast<const float2*>(color + cb2 + 2);
            const float2 dz = *reinterpret_cast<const float2*>(color + cb2 + 4);

            const float T0B = ex2(-(preB + c0B));
            const float w0B = T0B * (1.0f - u0B);
            const float w1B = (T0B * u1B) * (1.0f - u1B);

            r += w0B * da.x + w1B * dm.y;
            g += w0B * da.y + w1B * dz.x;
            b += w0B * dm.x + w1B * dz.y;
        }
    }

    // Warp reduction over lanes.
#pragma unroll
    for (int off = 16; off > 0; off >>= 1) {
        r += __shfl_xor_sync(0xffffffffu, r, off);
        g += __shfl_xor_sync(0xffffffffu, g, off);
        b += __shfl_xor_sync(0xffffffffu, b, off);
    }

    if (lane == 0) {
        out[ray * 3 + 0] = r;
        out[ray * 3 + 1] = g;
        out[ray * 3 + 2] = b;
    }
}

extern "C" void kernel_launch(void* const* d_in, const int* in_sizes, int n_in,
                              void* d_out, int out_size)
{
    // Identify buffers defensively by size. color is [N,128,3] -> uniquely 3x
    // larger than sdf/depth ([N,128] each).
    int ic = 0;
    for (int i = 1; i < n_in; ++i)
        if (in_sizes[i] > in_sizes[ic]) ic = i;

    int ia, ib;  // the two equal-size buffers, in index order
    if (ic == 0)      { ia = 1; ib = 2; }
    else if (ic == 1) { ia = 0; ib = 2; }
    else              { ia = 0; ib = 1; }

    int is, id;  // sdf index, depth index
    if (ic == 0) {
        // color first => name-sorted metadata (color, depth_values, sdf)
        id = ia; is = ib;
    } else {
        // insertion order (sdf, color, depth_values)
        is = ia; id = ib;
    }

    const float* sdf   = (const float*)d_in[is];
    const float* color = (const float*)d_in[ic];
    const float* depth = (const float*)d_in[id];
    float* out = (float*)d_out;

    const int N = out_size / 3;                   // 65536 rays
    const int threads = 256;                      // 8 warps = 8 rays / block
    const int blocks  = (N * 32 + threads - 1) / threads;
    volume_sdf_render_kernel<<<blocks, threads>>>(sdf, color, depth, out, N);
}

// round 12
// speedup vs baseline: 1.0196x; 1.0196x over previous
#include <cuda_runtime.h>
#include <cuda_bf16.h>

// VolumeSDF renderer: one warp per ray, 4 samples per lane (R9 shape),
// base-2 exponentials with pre-folded constants (R10 math).
//
//   density = ALPHA * LaplaceCDF(-sdf; BETA)
//   tau_s   = density_s * delta_s,  delta = diff(depth), last = 1e10
//   T_s     = exp(-inclusive_cumsum(tau)_s);  w_s = T_s*(1-exp(-tau_s+eps))
//   out[n]  = sum_s w_s * color[n,s,:]
//
// Byte savings: tail weight past prefix p telescopes to <= 2^-p, so lanes
// >=16 with prefix >= SKIP2 skip their color loads. Lanes 0-15 load color
// unconditionally, front-batched with sdf/depth (cum never crosses the
// threshold that early), keeping MLP high before the scan.
// Structure lesson from R7/R10: ONE serial memory exposure + one gated one;
// never three.

#define FAR_DELTA 1e10f
#define AEXP   28.853900817779268f   // (1/BETA)*log2(e) = 20*1.442695
#define DENS2  14.426950408889634f   // ALPHA*log2(e)
#define EPS2   1.442695041e-10f      // EPS*log2(e)
#define SKIP2  12.984255368006682f   // 9.0 nats in bits; 2^-12.98 = 1.2e-4

__device__ __forceinline__ float ex2(float x) {
    float y;
    asm("ex2.approx.ftz.f32 %0, %1;" : "=f"(y) : "f"(x));
    return y;
}

// tau per unit delta, in base-2 units: DENS2 * LaplaceCDF(-x, BETA)
__device__ __forceinline__ float dens2(float x) {
    const float e = 0.5f * ex2(-fabsf(x) * AEXP);
    const float cdf = (x > 0.0f) ? e : (1.0f - e);
    return DENS2 * cdf;
}

__global__ __launch_bounds__(256)
void volume_sdf_render_kernel(const float* __restrict__ sdf,
                              const float* __restrict__ color,
                              const float* __restrict__ depth,
                              float* __restrict__ out,
                              int N)
{
    const int gtid = blockIdx.x * blockDim.x + threadIdx.x;
    const int ray  = gtid >> 5;          // one warp per ray
    const int lane = threadIdx.x & 31;
    if (ray >= N) return;

    const int S = 128;
    const long long base  = (long long)ray * S + lane * 4;
    const long long cbase = base * 3;
    const bool early = (lane < 16);

    // ---- Front-batched loads: sdf, depth (+ color for lanes 0-15) ----
    const float4 s4 = *reinterpret_cast<const float4*>(sdf   + base);
    const float4 d4 = *reinterpret_cast<const float4*>(depth + base);
    float4 ca, cb, cc;
    if (early) {
        ca = *reinterpret_cast<const float4*>(color + cbase);
        cb = *reinterpret_cast<const float4*>(color + cbase + 4);
        cc = *reinterpret_cast<const float4*>(color + cbase + 8);
    }

    // Deltas. depth[4l+4] lives in the next lane's d4.x.
    const float dnext = __shfl_down_sync(0xffffffffu, d4.x, 1);
    float del[4];
    del[0] = d4.y - d4.x;
    del[1] = d4.z - d4.y;
    del[2] = d4.w - d4.z;
    del[3] = (lane == 31) ? FAR_DELTA : (dnext - d4.w);

    const float sd[4] = {s4.x, s4.y, s4.z, s4.w};

    // tau in base-2 units; u_i = 2^(-tau2_i + eps2) = 1 - trans_i.
    float tau[4], u[4];
#pragma unroll
    for (int i = 0; i < 4; ++i) {
        tau[i] = dens2(sd[i]) * del[i];
        u[i]   = ex2(-tau[i] + EPS2);
    }

    // Per-lane inclusive cumsum (base-2 units).
    const float c0 = tau[0];
    const float c1 = c0 + tau[1];
    const float c2 = c1 + tau[2];
    const float c3 = c2 + tau[3];

    // Warp inclusive scan of lane totals.
    float incl = c3;
#pragma unroll
    for (int off = 1; off < 32; off <<= 1) {
        const float v = __shfl_up_sync(0xffffffffu, incl, off);
        if (lane >= off) incl += v;
    }
    // Exclusive prefix from the PREVIOUS lane's inclusive value. Never by
    // subtraction: lane 31's c3 holds the far-delta tau and the subtraction
    // catastrophically cancels (R1/R2 rel_err=0.33 bug).
    float prefix = __shfl_up_sync(0xffffffffu, incl, 1);
    if (lane == 0) prefix = 0.0f;

    // Late lanes: load color only if the tail bound 2^-prefix is significant.
    const bool have = early || (prefix < SKIP2);
    if (!early && have) {
        ca = *reinterpret_cast<const float4*>(color + cbase);
        cb = *reinterpret_cast<const float4*>(color + cbase + 4);
        cc = *reinterpret_cast<const float4*>(color + cbase + 8);
    }

    float r = 0.0f, g = 0.0f, b = 0.0f;
    if (have) {
        // Telescoping transmittance: T0 = 2^-(prefix+c0); T_{i+1} = T_i*u_{i+1}
        // (the eps factor in u is ~1+1e-10, negligible). One EX2 total.
        const float T0 = ex2(-(prefix + c0));
        const float T1 = T0 * u[1];
        const float T2 = T1 * u[2];
        const float T3 = T2 * u[3];
        const float w0 = T0 * (1.0f - u[0]);
        const float w1 = T1 * (1.0f - u[1]);
        const float w2 = T2 * (1.0f - u[2]);
        const float w3 = T3 * (1.0f - u[3]);

        // sample0=(ca.x,ca.y,ca.z) sample1=(ca.w,cb.x,cb.y)
        // sample2=(cb.z,cb.w,cc.x) sample3=(cc.y,cc.z,cc.w)
        r = w0 * ca.x + w1 * ca.w + w2 * cb.z + w3 * cc.y;
        g = w0 * ca.y + w1 * cb.x + w2 * cb.w + w3 * cc.z;
        b = w0 * ca.z + w1 * cb.y + w2 * cc.x + w3 * cc.w;
    }

    // Warp reduction over lanes (samples).
#pragma unroll
    for (int off = 16; off > 0; off >>= 1) {
        r += __shfl_xor_sync(0xffffffffu, r, off);
        g += __shfl_xor_sync(0xffffffffu, g, off);
        b += __shfl_xor_sync(0xffffffffu, b, off);
    }

    if (lane == 0) {
        out[ray * 3 + 0] = r;
        out[ray * 3 + 1] = g;
        out[ray * 3 + 2] = b;
    }
}

extern "C" void kernel_launch(void* const* d_in, const int* in_sizes, int n_in,
                              void* d_out, int out_size)
{
    // Identify buffers defensively by size. color is [N,128,3] -> uniquely 3x
    // larger than sdf/depth ([N,128] each).
    int ic = 0;
    for (int i = 1; i < n_in; ++i)
        if (in_sizes[i] > in_sizes[ic]) ic = i;

    int ia, ib;  // the two equal-size buffers, in index order
    if (ic == 0)      { ia = 1; ib = 2; }
    else if (ic == 1) { ia = 0; ib = 2; }
    else              { ia = 0; ib = 1; }

    int is, id;  // sdf index, depth index
    if (ic == 0) {
        // color first => name-sorted metadata (color, depth_values, sdf)
        id = ia; is = ib;
    } else {
        // insertion order (sdf, color, depth_values)
        is = ia; id = ib;
    }

    const float* sdf   = (const float*)d_in[is];
    const float* color = (const float*)d_in[ic];
    const float* depth = (const float*)d_in[id];
    float* out = (float*)d_out;

    const int N = out_size / 3;                   // 65536 rays
    const int threads = 256;                      // 8 warps = 8 rays / block
    const int blocks  = (N * 32 + threads - 1) / threads;
    volume_sdf_render_kernel<<<blocks, threads>>>(sdf, color, depth, out, N);
}